// round 2
// baseline (speedup 1.0000x reference)
#include <cuda_runtime.h>
#include <math.h>

#define BATCH 4096
#define DIM   5000
#define HID   512
#define ZDIM  64

#define MU_OFF   (BATCH * DIM)            // 20480000
#define LV_OFF   (MU_OFF + BATCH * ZDIM)  // 20742144

// ---------------- scratch (device globals; allocation-free) ----------------
__device__ float g_h [BATCH * HID];
__device__ float g_mean[HID];
__device__ float g_rstd[HID];
__device__ float g_w [BATCH * DIM];
__device__ float g_xm[BATCH * DIM];
__device__ float g_e1[BATCH * 2 * HID];
__device__ float g_e2[BATCH * HID];
__device__ float g_e3[BATCH * HID];
__device__ float g_mt[BATCH * 2 * ZDIM];   // packed mu|logvar pre-activations
__device__ float g_z [BATCH * ZDIM];
__device__ float g_d1[BATCH * 2 * HID];
__device__ float g_hw[HID * 2 * ZDIM];     // packed head weights [512,128]
__device__ float g_hb[2 * ZDIM];           // packed head bias

// ---------------- SGEMM: C[M,N] = A[M,K] @ B[K,N] + bias, epilogue ----------
// BM=BN=128, BK=8, 256 threads, 8x8 per thread. M,K assumed %8==0 (true for
// all shapes here); N guarded.
template<int EPI>   // 0 = none, 2 = leaky(0.01), 3 = sigmoid
__global__ void __launch_bounds__(256)
sgemm_kernel(const float* __restrict__ A, const float* __restrict__ Bm,
             const float* __restrict__ bias, float* __restrict__ C,
             int M, int N, int K)
{
    __shared__ float As[8][128];
    __shared__ float Bs[8][128];

    const int tid  = threadIdx.x;
    const int row0 = blockIdx.y * 128;
    const int col0 = blockIdx.x * 128;

    const int ar = tid >> 1, ac = (tid & 1) * 4;   // A tile load coords
    const int br = tid >> 5, bc = (tid & 31) * 4;  // B tile load coords

    float acc[8][8];
#pragma unroll
    for (int i = 0; i < 8; i++)
#pragma unroll
        for (int j = 0; j < 8; j++) acc[i][j] = 0.f;

    const int rb = (tid >> 4) * 8;   // fragment row base in tile
    const int cb = (tid & 15) * 8;   // fragment col base in tile

    for (int k0 = 0; k0 < K; k0 += 8) {
        float4 av = *(const float4*)(A + (size_t)(row0 + ar) * K + k0 + ac);
        As[ac + 0][ar] = av.x;
        As[ac + 1][ar] = av.y;
        As[ac + 2][ar] = av.z;
        As[ac + 3][ar] = av.w;
#pragma unroll
        for (int i = 0; i < 4; i++) {
            int c = col0 + bc + i;
            Bs[br][bc + i] = (c < N) ? Bm[(size_t)(k0 + br) * N + c] : 0.f;
        }
        __syncthreads();
#pragma unroll
        for (int kk = 0; kk < 8; kk++) {
            float a[8], b[8];
#pragma unroll
            for (int i = 0; i < 8; i++) a[i] = As[kk][rb + i];
#pragma unroll
            for (int j = 0; j < 8; j++) b[j] = Bs[kk][cb + j];
#pragma unroll
            for (int i = 0; i < 8; i++)
#pragma unroll
                for (int j = 0; j < 8; j++) acc[i][j] += a[i] * b[j];
        }
        __syncthreads();
    }

#pragma unroll
    for (int i = 0; i < 8; i++) {
        int r = row0 + rb + i;
#pragma unroll
        for (int j = 0; j < 8; j++) {
            int c = col0 + cb + j;
            if (c < N) {
                float v = acc[i][j] + bias[c];
                if (EPI == 2) v = (v > 0.f) ? v : 0.01f * v;
                if (EPI == 3) v = 1.0f / (1.0f + expf(-v));
                C[(size_t)r * N + c] = v;
            }
        }
    }
}

// ---------------- BatchNorm stats (two-pass, biased var) --------------------
__global__ void bn_stats_kernel(const float* __restrict__ h,
                                float* __restrict__ mean,
                                float* __restrict__ rstd)
{
    int c = blockIdx.x;
    __shared__ float sm[256];
    float s = 0.f;
    for (int r = threadIdx.x; r < BATCH; r += 256) s += h[(size_t)r * HID + c];
    sm[threadIdx.x] = s; __syncthreads();
    for (int o = 128; o; o >>= 1) {
        if (threadIdx.x < o) sm[threadIdx.x] += sm[threadIdx.x + o];
        __syncthreads();
    }
    float m = sm[0] * (1.0f / BATCH);
    __syncthreads();
    float v = 0.f;
    for (int r = threadIdx.x; r < BATCH; r += 256) {
        float d = h[(size_t)r * HID + c] - m;
        v += d * d;
    }
    sm[threadIdx.x] = v; __syncthreads();
    for (int o = 128; o; o >>= 1) {
        if (threadIdx.x < o) sm[threadIdx.x] += sm[threadIdx.x + o];
        __syncthreads();
    }
    if (threadIdx.x == 0) {
        mean[c] = m;
        rstd[c] = rsqrtf(sm[0] * (1.0f / BATCH) + 1e-5f);
    }
}

__global__ void bn_apply_kernel(float* __restrict__ h,
                                const float* __restrict__ mean,
                                const float* __restrict__ rstd,
                                const float* __restrict__ g,
                                const float* __restrict__ b)
{
    int i = blockIdx.x * 256 + threadIdx.x;
    if (i < BATCH * HID) {
        int c = i & (HID - 1);
        float v = (h[i] - mean[c]) * rstd[c] * g[c] + b[c];
        h[i] = (v > 0.f) ? v : 0.f;
    }
}

// ---------------- Gumbel key injection -------------------------------------
__global__ void gumbel_kernel(float* __restrict__ w, const float* __restrict__ u)
{
    int i = blockIdx.x * 256 + threadIdx.x;
    if (i < BATCH * DIM) {
        float uu = u[i] + 1e-30f;   // (1-eps)*u + eps ; (1-eps)==1 in fp32
        w[i] += logf(-logf(uu));
    }
}

// ---------------- continuous top-k (K=50, T=0.1), fully in registers -------
// One CTA (256 thr) per row. Maintain s = exp((w - max)/T); the recurrence
// w += log(max(1-p,eps)) is equivalent to s *= m^(1/T) = m^10 (4 muls).
__device__ __forceinline__ float block_reduce_sum(float v, float* sm)
{
#pragma unroll
    for (int o = 16; o; o >>= 1) v += __shfl_xor_sync(0xffffffffu, v, o);
    int wid = threadIdx.x >> 5, lid = threadIdx.x & 31;
    if (lid == 0) sm[wid] = v;
    __syncthreads();
    if (wid == 0) {
        v = (lid < 8) ? sm[lid] : 0.f;
#pragma unroll
        for (int o = 4; o; o >>= 1) v += __shfl_xor_sync(0xffffffffu, v, o);
        if (lid == 0) sm[0] = v;
    }
    __syncthreads();
    v = sm[0];
    __syncthreads();
    return v;
}

__device__ __forceinline__ float block_reduce_max(float v, float* sm)
{
#pragma unroll
    for (int o = 16; o; o >>= 1) v = fmaxf(v, __shfl_xor_sync(0xffffffffu, v, o));
    int wid = threadIdx.x >> 5, lid = threadIdx.x & 31;
    if (lid == 0) sm[wid] = v;
    __syncthreads();
    if (wid == 0) {
        v = (lid < 8) ? sm[lid] : -INFINITY;
#pragma unroll
        for (int o = 4; o; o >>= 1) v = fmaxf(v, __shfl_xor_sync(0xffffffffu, v, o));
        if (lid == 0) sm[0] = v;
    }
    __syncthreads();
    v = sm[0];
    __syncthreads();
    return v;
}

#define NPT 20   // ceil(5000/256)

__global__ void __launch_bounds__(256)
topk_kernel(const float* __restrict__ w, const float* __restrict__ x,
            float* __restrict__ xm)
{
    __shared__ float sm[8];
    const int row  = blockIdx.x;
    const size_t base = (size_t)row * DIM;
    const int tid  = threadIdx.x;

    float s[NPT], sub[NPT];

    // init: s = exp((w - rowmax) * 10)
    float wv[NPT];
    float wmax = -INFINITY;
#pragma unroll
    for (int k = 0; k < NPT; k++) {
        int j = tid + k * 256;
        wv[k] = (j < DIM) ? w[base + j] : -INFINITY;
        wmax = fmaxf(wmax, wv[k]);
    }
    wmax = block_reduce_max(wmax, sm);

    float Sl = 0.f;
#pragma unroll
    for (int k = 0; k < NPT; k++) {
        int j = tid + k * 256;
        s[k] = (j < DIM) ? expf((wv[k] - wmax) * 10.0f) : 0.f;
        sub[k] = 0.f;
        Sl += s[k];
    }
    float S = block_reduce_sum(Sl, sm);

    for (int it = 0; it < 50; it++) {
        float inv = 1.0f / S;
        float ns = 0.f;
#pragma unroll
        for (int k = 0; k < NPT; k++) {
            float p = s[k] * inv;
            sub[k] += p;
            float m = fmaxf(1.0f - p, 1e-30f);
            float m2 = m * m;
            float m4 = m2 * m2;
            float m8 = m4 * m4;
            s[k] *= m8 * m2;     // m^10
            ns += s[k];
        }
        S = block_reduce_sum(ns, sm);
    }

#pragma unroll
    for (int k = 0; k < NPT; k++) {
        int j = tid + k * 256;
        if (j < DIM) xm[base + j] = x[base + j] * sub[k];
    }
}

// ---------------- pack mean/logvar heads into one [512,128] GEMM -----------
__global__ void pack_heads_kernel(const float* __restrict__ mw,
                                  const float* __restrict__ mb,
                                  const float* __restrict__ lw,
                                  const float* __restrict__ lb,
                                  float* __restrict__ pw,
                                  float* __restrict__ pb)
{
    int i = blockIdx.x * 256 + threadIdx.x;
    if (i < HID * 2 * ZDIM) {
        int k = i >> 7;          // / 128
        int j = i & 127;
        pw[i] = (j < ZDIM) ? mw[k * ZDIM + j] : lw[k * ZDIM + (j - ZDIM)];
    }
    if (i < 2 * ZDIM) pb[i] = (i < ZDIM) ? mb[i] : lb[i - ZDIM];
}

// ---------------- reparameterize + emit latent outputs ---------------------
__global__ void zrep_kernel(const float* __restrict__ mt,
                            const float* __restrict__ eps,
                            float* __restrict__ out,
                            float* __restrict__ z)
{
    int i = blockIdx.x * 256 + threadIdx.x;
    if (i < BATCH * ZDIM) {
        int r = i >> 6;          // / 64
        int c = i & 63;
        float mu = mt[r * 128 + c];
        float lv = mt[r * 128 + ZDIM + c];
        out[MU_OFF + i] = mu;
        out[LV_OFF + i] = lv;
        z[i] = mu + eps[i] * expf(0.5f * lv);
    }
}

// ---------------- launch -----------------------------------------------------
static inline dim3 gemm_grid(int M, int N) {
    return dim3((N + 127) / 128, (M + 127) / 128);
}

extern "C" void kernel_launch(void* const* d_in, const int* in_sizes, int n_in,
                              void* d_out, int out_size)
{
    const float* x       = (const float*)d_in[0];
    const float* noise_u = (const float*)d_in[1];
    const float* eps     = (const float*)d_in[2];
    const float* wc_w1   = (const float*)d_in[3];
    const float* wc_b1   = (const float*)d_in[4];
    const float* bn_g    = (const float*)d_in[5];
    const float* bn_b    = (const float*)d_in[6];
    const float* wc_w2   = (const float*)d_in[7];
    const float* wc_b2   = (const float*)d_in[8];
    const float* enc_w1  = (const float*)d_in[9];
    const float* enc_b1  = (const float*)d_in[10];
    const float* enc_w2  = (const float*)d_in[11];
    const float* enc_b2  = (const float*)d_in[12];
    const float* enc_w3  = (const float*)d_in[13];
    const float* enc_b3  = (const float*)d_in[14];
    const float* enc_w4  = (const float*)d_in[15];
    const float* enc_b4  = (const float*)d_in[16];
    const float* mean_w  = (const float*)d_in[17];
    const float* mean_b  = (const float*)d_in[18];
    const float* lv_w    = (const float*)d_in[19];
    const float* lv_b    = (const float*)d_in[20];
    const float* dec_w1  = (const float*)d_in[21];
    const float* dec_b1  = (const float*)d_in[22];
    const float* dec_w2  = (const float*)d_in[23];
    const float* dec_b2  = (const float*)d_in[24];
    float* out = (float*)d_out;

    float *h, *mean, *rstd, *w, *xm, *e1, *e2, *e3, *mt, *z, *d1, *hw, *hb;
    cudaGetSymbolAddress((void**)&h,    g_h);
    cudaGetSymbolAddress((void**)&mean, g_mean);
    cudaGetSymbolAddress((void**)&rstd, g_rstd);
    cudaGetSymbolAddress((void**)&w,    g_w);
    cudaGetSymbolAddress((void**)&xm,   g_xm);
    cudaGetSymbolAddress((void**)&e1,   g_e1);
    cudaGetSymbolAddress((void**)&e2,   g_e2);
    cudaGetSymbolAddress((void**)&e3,   g_e3);
    cudaGetSymbolAddress((void**)&mt,   g_mt);
    cudaGetSymbolAddress((void**)&z,    g_z);
    cudaGetSymbolAddress((void**)&d1,   g_d1);
    cudaGetSymbolAddress((void**)&hw,   g_hw);
    cudaGetSymbolAddress((void**)&hb,   g_hb);

    // 1) weight creator
    sgemm_kernel<0><<<gemm_grid(BATCH, HID), 256>>>(x, wc_w1, wc_b1, h,
                                                    BATCH, HID, DIM);
    bn_stats_kernel<<<HID, 256>>>(h, mean, rstd);
    bn_apply_kernel<<<(BATCH * HID + 255) / 256, 256>>>(h, mean, rstd, bn_g, bn_b);
    sgemm_kernel<0><<<gemm_grid(BATCH, DIM), 256>>>(h, wc_w2, wc_b2, w,
                                                    BATCH, DIM, HID);
    gumbel_kernel<<<(BATCH * DIM + 255) / 256, 256>>>(w, noise_u);

    // 2) continuous top-k + mask
    topk_kernel<<<BATCH, 256>>>(w, x, xm);

    // 3) encoder
    sgemm_kernel<2><<<gemm_grid(BATCH, 2 * HID), 256>>>(xm, enc_w1, enc_b1, e1,
                                                        BATCH, 2 * HID, DIM);
    sgemm_kernel<2><<<gemm_grid(BATCH, HID), 256>>>(e1, enc_w2, enc_b2, e2,
                                                    BATCH, HID, 2 * HID);
    sgemm_kernel<2><<<gemm_grid(BATCH, HID), 256>>>(e2, enc_w3, enc_b3, e3,
                                                    BATCH, HID, HID);
    sgemm_kernel<2><<<gemm_grid(BATCH, HID), 256>>>(e3, enc_w4, enc_b4, e2,
                                                    BATCH, HID, HID);

    // 4) latent heads (packed), reparameterize
    pack_heads_kernel<<<(HID * 2 * ZDIM + 255) / 256, 256>>>(mean_w, mean_b,
                                                             lv_w, lv_b, hw, hb);
    sgemm_kernel<0><<<gemm_grid(BATCH, 2 * ZDIM), 256>>>(e2, hw, hb, mt,
                                                         BATCH, 2 * ZDIM, HID);
    zrep_kernel<<<(BATCH * ZDIM + 255) / 256, 256>>>(mt, eps, out, z);

    // 5) decoder
    sgemm_kernel<2><<<gemm_grid(BATCH, 2 * HID), 256>>>(z, dec_w1, dec_b1, d1,
                                                        BATCH, 2 * HID, ZDIM);
    sgemm_kernel<3><<<gemm_grid(BATCH, DIM), 256>>>(d1, dec_w2, dec_b2, out,
                                                    BATCH, DIM, 2 * HID);
}

// round 3
// speedup vs baseline: 1.3560x; 1.3560x over previous
#include <cuda_runtime.h>
#include <math.h>

#define BATCH 4096
#define DIM   5000
#define HID   512
#define ZDIM  64

#define MU_OFF   (BATCH * DIM)
#define LV_OFF   (MU_OFF + BATCH * ZDIM)

// ---------------- scratch (device globals; allocation-free) ----------------
__device__ float g_h [BATCH * HID];
__device__ float g_mean[HID];
__device__ float g_rstd[HID];
__device__ float g_w [BATCH * DIM];
__device__ float g_xm[BATCH * DIM];
__device__ float g_e1[BATCH * 2 * HID];
__device__ float g_e2[BATCH * HID];
__device__ float g_e3[BATCH * HID];
__device__ float g_mt[BATCH * 2 * ZDIM];
__device__ float g_z [BATCH * ZDIM];
__device__ float g_d1[BATCH * 2 * HID];
__device__ float g_hw[HID * 2 * ZDIM];
__device__ float g_hb[2 * ZDIM];

// ---------------- tf32 helpers ---------------------------------------------
__device__ __forceinline__ float f2tf(float v) {
    unsigned r;
    asm("cvt.rna.tf32.f32 %0, %1;" : "=r"(r) : "f"(v));
    return __uint_as_float(r);
}

// ---------------- 3xTF32 tensor-core GEMM ----------------------------------
// C[M,N] = A[M,K] @ B[K,N] + bias, epilogue.
// 128x128 tile, true-BK=16. Each fp32 value split into hi/lo tf32; smem holds
// [hi|lo] (16+16 k-cols). Six m16n8k8 k-steps per chunk realize the 3 products
// (Ah*Bh, Ah*Bl, Al*Bh) via k-index remapping. B stored transposed [n][k] so
// both fragment loads are LDS.64. Stride 36 => conflict-free (36 mod 32 = 4).
#define ASTRIDE 36
#define BSTRIDE 36

template<int EPI>   // 0=none, 2=leaky, 3=sigmoid, 4=gumbel(+log(-log u))
__global__ void __launch_bounds__(256, 2)
mma_gemm(const float* __restrict__ A, const float* __restrict__ Bm,
         const float* __restrict__ bias, const float* __restrict__ U,
         float* __restrict__ C, int M, int N, int K)
{
    __shared__ __align__(16) float As[128 * ASTRIDE];
    __shared__ __align__(16) float Bs[128 * BSTRIDE];

    const int tid  = threadIdx.x;
    const int lane = tid & 31;
    const int wid  = tid >> 5;
    const int wm   = wid >> 2;   // 0..1 : warp row (64 rows each)
    const int wn   = wid & 3;    // 0..3 : warp col (32 cols each)
    const int g    = lane >> 2;  // group id 0..7
    const int t    = lane & 3;   // thread-in-group

    const int row0 = blockIdx.y * 128;
    const int col0 = blockIdx.x * 128;

    float acc[4][4][4];
#pragma unroll
    for (int mi = 0; mi < 4; mi++)
#pragma unroll
        for (int ni = 0; ni < 4; ni++)
#pragma unroll
            for (int e = 0; e < 4; e++) acc[mi][ni][e] = 0.f;

    for (int k0 = 0; k0 < K; k0 += 16) {
        // ---- load A tile (128 x 16 true) -> hi cols [0,16), lo cols [16,32)
#pragma unroll
        for (int it = 0; it < 2; it++) {
            int idx = tid + it * 256;
            int r   = idx >> 2;
            int cq  = (idx & 3) * 4;
            const float* src = A + (size_t)(row0 + r) * K + k0 + cq;
            float v[4];
            if (k0 + cq + 3 < K) {
                float4 q = *(const float4*)src;
                v[0] = q.x; v[1] = q.y; v[2] = q.z; v[3] = q.w;
            } else {
#pragma unroll
                for (int i = 0; i < 4; i++) v[i] = (k0 + cq + i < K) ? src[i] : 0.f;
            }
            float hi[4], lo[4];
#pragma unroll
            for (int i = 0; i < 4; i++) { hi[i] = f2tf(v[i]); lo[i] = f2tf(v[i] - hi[i]); }
            *(float4*)&As[r * ASTRIDE + cq]      = make_float4(hi[0], hi[1], hi[2], hi[3]);
            *(float4*)&As[r * ASTRIDE + 16 + cq] = make_float4(lo[0], lo[1], lo[2], lo[3]);
        }
        // ---- load B tile (16 x 128 true), store transposed [n][k]
#pragma unroll
        for (int it = 0; it < 2; it++) {
            int idx = tid + it * 256;
            int kr  = idx >> 5;            // 0..15
            int c4  = (idx & 31) * 4;      // 0..124
            const float* src = Bm + (size_t)(k0 + kr) * N + col0 + c4;
            bool kok = (k0 + kr) < K;
            float v[4];
            if (kok && (col0 + c4 + 3 < N)) {
                float4 q = *(const float4*)src;
                v[0] = q.x; v[1] = q.y; v[2] = q.z; v[3] = q.w;
            } else {
#pragma unroll
                for (int i = 0; i < 4; i++)
                    v[i] = (kok && (col0 + c4 + i < N)) ? src[i] : 0.f;
            }
#pragma unroll
            for (int i = 0; i < 4; i++) {
                float hi = f2tf(v[i]);
                float lo = f2tf(v[i] - hi);
                Bs[(c4 + i) * BSTRIDE + kr]      = hi;
                Bs[(c4 + i) * BSTRIDE + 16 + kr] = lo;
            }
        }
        __syncthreads();

        // k-step maps: (Ah,Bh) x2, (Ah,Bl) x2, (Al,Bh) x2
        const int acm[6] = {0, 8, 0,  8,  16, 24};
        const int bcm[6] = {0, 8, 16, 24, 0,  8};
#pragma unroll
        for (int ks = 0; ks < 6; ks++) {
            const int ak = acm[ks] + 2 * t;
            const int bk = bcm[ks] + 2 * t;
            unsigned a[4][4];
#pragma unroll
            for (int mi = 0; mi < 4; mi++) {
                int rb = (wm * 64 + mi * 16 + g) * ASTRIDE;
                float2 p0 = *(const float2*)&As[rb + ak];
                float2 p1 = *(const float2*)&As[rb + 8 * ASTRIDE + ak];
                a[mi][0] = __float_as_uint(p0.x);
                a[mi][2] = __float_as_uint(p0.y);
                a[mi][1] = __float_as_uint(p1.x);
                a[mi][3] = __float_as_uint(p1.y);
            }
            unsigned b[4][2];
#pragma unroll
            for (int ni = 0; ni < 4; ni++) {
                int nb = (wn * 32 + ni * 8 + g) * BSTRIDE;
                float2 q = *(const float2*)&Bs[nb + bk];
                b[ni][0] = __float_as_uint(q.x);
                b[ni][1] = __float_as_uint(q.y);
            }
#pragma unroll
            for (int mi = 0; mi < 4; mi++)
#pragma unroll
                for (int ni = 0; ni < 4; ni++) {
                    asm volatile(
                        "mma.sync.aligned.m16n8k8.row.col.f32.tf32.tf32.f32 "
                        "{%0,%1,%2,%3}, {%4,%5,%6,%7}, {%8,%9}, {%0,%1,%2,%3};"
                        : "+f"(acc[mi][ni][0]), "+f"(acc[mi][ni][1]),
                          "+f"(acc[mi][ni][2]), "+f"(acc[mi][ni][3])
                        : "r"(a[mi][0]), "r"(a[mi][1]), "r"(a[mi][2]), "r"(a[mi][3]),
                          "r"(b[ni][0]), "r"(b[ni][1]));
                }
        }
        __syncthreads();
    }

    // ---- epilogue
#pragma unroll
    for (int mi = 0; mi < 4; mi++) {
        int r0 = row0 + wm * 64 + mi * 16 + g;
#pragma unroll
        for (int ni = 0; ni < 4; ni++) {
            int c0 = col0 + wn * 32 + ni * 8 + 2 * t;
#pragma unroll
            for (int e = 0; e < 4; e++) {
                int r = r0 + (e >> 1) * 8;
                int c = c0 + (e & 1);
                if (c < N) {
                    float v = acc[mi][ni][e] + bias[c];
                    if (EPI == 2) v = (v > 0.f) ? v : 0.01f * v;
                    if (EPI == 3) v = 1.0f / (1.0f + expf(-v));
                    if (EPI == 4) v += logf(-logf(U[(size_t)r * N + c] + 1e-30f));
                    C[(size_t)r * N + c] = v;
                }
            }
        }
    }
}

// ---------------- BatchNorm stats (two-pass, biased var) --------------------
__global__ void bn_stats_kernel(const float* __restrict__ h,
                                float* __restrict__ mean,
                                float* __restrict__ rstd)
{
    int c = blockIdx.x;
    __shared__ float sm[256];
    float s = 0.f;
    for (int r = threadIdx.x; r < BATCH; r += 256) s += h[(size_t)r * HID + c];
    sm[threadIdx.x] = s; __syncthreads();
    for (int o = 128; o; o >>= 1) {
        if (threadIdx.x < o) sm[threadIdx.x] += sm[threadIdx.x + o];
        __syncthreads();
    }
    float m = sm[0] * (1.0f / BATCH);
    __syncthreads();
    float v = 0.f;
    for (int r = threadIdx.x; r < BATCH; r += 256) {
        float d = h[(size_t)r * HID + c] - m;
        v += d * d;
    }
    sm[threadIdx.x] = v; __syncthreads();
    for (int o = 128; o; o >>= 1) {
        if (threadIdx.x < o) sm[threadIdx.x] += sm[threadIdx.x + o];
        __syncthreads();
    }
    if (threadIdx.x == 0) {
        mean[c] = m;
        rstd[c] = rsqrtf(sm[0] * (1.0f / BATCH) + 1e-5f);
    }
}

__global__ void bn_apply_kernel(float* __restrict__ h,
                                const float* __restrict__ mean,
                                const float* __restrict__ rstd,
                                const float* __restrict__ g,
                                const float* __restrict__ b)
{
    int i = blockIdx.x * 256 + threadIdx.x;
    if (i < BATCH * HID) {
        int c = i & (HID - 1);
        float v = (h[i] - mean[c]) * rstd[c] * g[c] + b[c];
        h[i] = (v > 0.f) ? v : 0.f;
    }
}

// ---------------- continuous top-k (K=50, T=0.1), register-resident --------
__device__ __forceinline__ float block_reduce_sum(float v, float* sm)
{
#pragma unroll
    for (int o = 16; o; o >>= 1) v += __shfl_xor_sync(0xffffffffu, v, o);
    int wid = threadIdx.x >> 5, lid = threadIdx.x & 31;
    if (lid == 0) sm[wid] = v;
    __syncthreads();
    if (wid == 0) {
        v = (lid < 8) ? sm[lid] : 0.f;
#pragma unroll
        for (int o = 4; o; o >>= 1) v += __shfl_xor_sync(0xffffffffu, v, o);
        if (lid == 0) sm[0] = v;
    }
    __syncthreads();
    v = sm[0];
    __syncthreads();
    return v;
}

__device__ __forceinline__ float block_reduce_max(float v, float* sm)
{
#pragma unroll
    for (int o = 16; o; o >>= 1) v = fmaxf(v, __shfl_xor_sync(0xffffffffu, v, o));
    int wid = threadIdx.x >> 5, lid = threadIdx.x & 31;
    if (lid == 0) sm[wid] = v;
    __syncthreads();
    if (wid == 0) {
        v = (lid < 8) ? sm[lid] : -INFINITY;
#pragma unroll
        for (int o = 4; o; o >>= 1) v = fmaxf(v, __shfl_xor_sync(0xffffffffu, v, o));
        if (lid == 0) sm[0] = v;
    }
    __syncthreads();
    v = sm[0];
    __syncthreads();
    return v;
}

#define NPT 20

__global__ void __launch_bounds__(256)
topk_kernel(const float* __restrict__ w, const float* __restrict__ x,
            float* __restrict__ xm)
{
    __shared__ float sm[8];
    const int row  = blockIdx.x;
    const size_t base = (size_t)row * DIM;
    const int tid  = threadIdx.x;

    float s[NPT], sub[NPT];
    float wv[NPT];
    float wmax = -INFINITY;
#pragma unroll
    for (int k = 0; k < NPT; k++) {
        int j = tid + k * 256;
        wv[k] = (j < DIM) ? w[base + j] : -INFINITY;
        wmax = fmaxf(wmax, wv[k]);
    }
    wmax = block_reduce_max(wmax, sm);

    float Sl = 0.f;
#pragma unroll
    for (int k = 0; k < NPT; k++) {
        int j = tid + k * 256;
        s[k] = (j < DIM) ? expf((wv[k] - wmax) * 10.0f) : 0.f;
        sub[k] = 0.f;
        Sl += s[k];
    }
    float S = block_reduce_sum(Sl, sm);

    for (int it = 0; it < 50; it++) {
        float inv = 1.0f / S;
        float ns = 0.f;
#pragma unroll
        for (int k = 0; k < NPT; k++) {
            float p = s[k] * inv;
            sub[k] += p;
            float m = fmaxf(1.0f - p, 1e-30f);
            float m2 = m * m;
            float m4 = m2 * m2;
            float m8 = m4 * m4;
            s[k] *= m8 * m2;     // m^10
            ns += s[k];
        }
        S = block_reduce_sum(ns, sm);
    }

#pragma unroll
    for (int k = 0; k < NPT; k++) {
        int j = tid + k * 256;
        if (j < DIM) xm[base + j] = x[base + j] * sub[k];
    }
}

// ---------------- pack mean/logvar heads into one [512,128] GEMM -----------
__global__ void pack_heads_kernel(const float* __restrict__ mw,
                                  const float* __restrict__ mb,
                                  const float* __restrict__ lw,
                                  const float* __restrict__ lb,
                                  float* __restrict__ pw,
                                  float* __restrict__ pb)
{
    int i = blockIdx.x * 256 + threadIdx.x;
    if (i < HID * 2 * ZDIM) {
        int k = i >> 7;
        int j = i & 127;
        pw[i] = (j < ZDIM) ? mw[k * ZDIM + j] : lw[k * ZDIM + (j - ZDIM)];
    }
    if (i < 2 * ZDIM) pb[i] = (i < ZDIM) ? mb[i] : lb[i - ZDIM];
}

// ---------------- reparameterize + emit latent outputs ---------------------
__global__ void zrep_kernel(const float* __restrict__ mt,
                            const float* __restrict__ eps,
                            float* __restrict__ out,
                            float* __restrict__ z)
{
    int i = blockIdx.x * 256 + threadIdx.x;
    if (i < BATCH * ZDIM) {
        int r = i >> 6;
        int c = i & 63;
        float mu = mt[r * 128 + c];
        float lv = mt[r * 128 + ZDIM + c];
        out[MU_OFF + i] = mu;
        out[LV_OFF + i] = lv;
        z[i] = mu + eps[i] * expf(0.5f * lv);
    }
}

// ---------------- launch ----------------------------------------------------
static inline dim3 gemm_grid(int M, int N) {
    return dim3((N + 127) / 128, (M + 127) / 128);
}

extern "C" void kernel_launch(void* const* d_in, const int* in_sizes, int n_in,
                              void* d_out, int out_size)
{
    const float* x       = (const float*)d_in[0];
    const float* noise_u = (const float*)d_in[1];
    const float* eps     = (const float*)d_in[2];
    const float* wc_w1   = (const float*)d_in[3];
    const float* wc_b1   = (const float*)d_in[4];
    const float* bn_g    = (const float*)d_in[5];
    const float* bn_b    = (const float*)d_in[6];
    const float* wc_w2   = (const float*)d_in[7];
    const float* wc_b2   = (const float*)d_in[8];
    const float* enc_w1  = (const float*)d_in[9];
    const float* enc_b1  = (const float*)d_in[10];
    const float* enc_w2  = (const float*)d_in[11];
    const float* enc_b2  = (const float*)d_in[12];
    const float* enc_w3  = (const float*)d_in[13];
    const float* enc_b3  = (const float*)d_in[14];
    const float* enc_w4  = (const float*)d_in[15];
    const float* enc_b4  = (const float*)d_in[16];
    const float* mean_w  = (const float*)d_in[17];
    const float* mean_b  = (const float*)d_in[18];
    const float* lv_w    = (const float*)d_in[19];
    const float* lv_b    = (const float*)d_in[20];
    const float* dec_w1  = (const float*)d_in[21];
    const float* dec_b1  = (const float*)d_in[22];
    const float* dec_w2  = (const float*)d_in[23];
    const float* dec_b2  = (const float*)d_in[24];
    float* out = (float*)d_out;

    float *h, *mean, *rstd, *w, *xm, *e1, *e2, *e3, *mt, *z, *d1, *hw, *hb;
    cudaGetSymbolAddress((void**)&h,    g_h);
    cudaGetSymbolAddress((void**)&mean, g_mean);
    cudaGetSymbolAddress((void**)&rstd, g_rstd);
    cudaGetSymbolAddress((void**)&w,    g_w);
    cudaGetSymbolAddress((void**)&xm,   g_xm);
    cudaGetSymbolAddress((void**)&e1,   g_e1);
    cudaGetSymbolAddress((void**)&e2,   g_e2);
    cudaGetSymbolAddress((void**)&e3,   g_e3);
    cudaGetSymbolAddress((void**)&mt,   g_mt);
    cudaGetSymbolAddress((void**)&z,    g_z);
    cudaGetSymbolAddress((void**)&d1,   g_d1);
    cudaGetSymbolAddress((void**)&hw,   g_hw);
    cudaGetSymbolAddress((void**)&hb,   g_hb);

    // 1) weight creator
    mma_gemm<0><<<gemm_grid(BATCH, HID), 256>>>(x, wc_w1, wc_b1, nullptr, h,
                                                BATCH, HID, DIM);
    bn_stats_kernel<<<HID, 256>>>(h, mean, rstd);
    bn_apply_kernel<<<(BATCH * HID + 255) / 256, 256>>>(h, mean, rstd, bn_g, bn_b);
    // GEMM2 with fused gumbel epilogue
    mma_gemm<4><<<gemm_grid(BATCH, DIM), 256>>>(h, wc_w2, wc_b2, noise_u, w,
                                                BATCH, DIM, HID);

    // 2) continuous top-k + mask
    topk_kernel<<<BATCH, 256>>>(w, x, xm);

    // 3) encoder
    mma_gemm<2><<<gemm_grid(BATCH, 2 * HID), 256>>>(xm, enc_w1, enc_b1, nullptr, e1,
                                                    BATCH, 2 * HID, DIM);
    mma_gemm<2><<<gemm_grid(BATCH, HID), 256>>>(e1, enc_w2, enc_b2, nullptr, e2,
                                                BATCH, HID, 2 * HID);
    mma_gemm<2><<<gemm_grid(BATCH, HID), 256>>>(e2, enc_w3, enc_b3, nullptr, e3,
                                                BATCH, HID, HID);
    mma_gemm<2><<<gemm_grid(BATCH, HID), 256>>>(e3, enc_w4, enc_b4, nullptr, e2,
                                                BATCH, HID, HID);

    // 4) latent heads (packed), reparameterize
    pack_heads_kernel<<<(HID * 2 * ZDIM + 255) / 256, 256>>>(mean_w, mean_b,
                                                             lv_w, lv_b, hw, hb);
    mma_gemm<0><<<gemm_grid(BATCH, 2 * ZDIM), 256>>>(e2, hw, hb, nullptr, mt,
                                                     BATCH, 2 * ZDIM, HID);
    zrep_kernel<<<(BATCH * ZDIM + 255) / 256, 256>>>(mt, eps, out, z);

    // 5) decoder
    mma_gemm<2><<<gemm_grid(BATCH, 2 * HID), 256>>>(z, dec_w1, dec_b1, nullptr, d1,
                                                    BATCH, 2 * HID, ZDIM);
    mma_gemm<3><<<gemm_grid(BATCH, DIM), 256>>>(d1, dec_w2, dec_b2, nullptr, out,
                                                BATCH, DIM, 2 * HID);
}